// round 2
// baseline (speedup 1.0000x reference)
#include <cuda_runtime.h>
#include <cuda_bf16.h>
#include <math.h>

// ---------------- problem constants ----------------
#define NOPEN 64
#define NNIN  16
#define MAXN  65536
#define DTH   0.025f           // dt*H = (1/4)*0.1

// ---------------- device scratch ----------------
__device__ float g_x[(size_t)MAXN * NOPEN];
__device__ float g_div[(size_t)MAXN * NOPEN];
__device__ float g_dinv[MAXN];
__device__ int   g_deg[MAXN];

// ---------------- f32x2 helpers ----------------
static __device__ __forceinline__ unsigned long long ffma2(unsigned long long a,
                                                           unsigned long long b,
                                                           unsigned long long c) {
    unsigned long long d;
    asm("fma.rn.f32x2 %0, %1, %2, %3;" : "=l"(d) : "l"(a), "l"(b), "l"(c));
    return d;
}
static __device__ __forceinline__ unsigned long long dup2(float x) {
    unsigned long long d;
    asm("mov.b64 %0, {%1, %1};" : "=l"(d) : "f"(x));
    return d;
}
static __device__ __forceinline__ float2 unpk(unsigned long long v) {
    float2 r;
    asm("mov.b64 {%0, %1}, %2;" : "=f"(r.x), "=f"(r.y) : "l"(v));
    return r;
}
static __device__ __forceinline__ unsigned long long pk(float x, float y) {
    unsigned long long d;
    asm("mov.b64 %0, {%1, %2};" : "=l"(d) : "f"(x), "f"(y));
    return d;
}

// ---------------- degree / norm ----------------
__global__ void deg_init_kernel(int nN) {
    int i = blockIdx.x * blockDim.x + threadIdx.x;
    if (i < nN) g_deg[i] = 1;
}
__global__ void deg_count_kernel(const int* __restrict__ jInd, int nE) {
    int i = blockIdx.x * blockDim.x + threadIdx.x;
    if (i < nE) atomicAdd(&g_deg[jInd[i]], 1);
}
__global__ void dinv_kernel(int nN) {
    int i = blockIdx.x * blockDim.x + threadIdx.x;
    if (i < nN) g_dinv[i] = rsqrtf((float)g_deg[i]);
}

// ---------------- x0 = relu(K1Nopen @ xn), coalesced thread-per-node -------
__global__ void x0_kernel(const float* __restrict__ xn, const float* __restrict__ K1,
                          int nN) {
    __shared__ float sK[NOPEN * NNIN];
    for (int idx = threadIdx.x; idx < NOPEN * NNIN; idx += blockDim.x)
        sK[idx] = K1[idx];
    __syncthreads();

    int n0     = blockIdx.x * blockDim.x + threadIdx.x;
    int stride = gridDim.x * blockDim.x;
    for (int n = n0; n < nN; n += stride) {
        float acc[NOPEN];
#pragma unroll
        for (int o = 0; o < NOPEN; o++) acc[o] = 0.f;
#pragma unroll
        for (int c = 0; c < NNIN; c++) {
            float xc = xn[(size_t)c * nN + n];   // coalesced across threads
#pragma unroll
            for (int o = 0; o < NOPEN; o++) acc[o] += sK[o * NNIN + c] * xc;
        }
        float4* dst = (float4*)&g_x[(size_t)n * NOPEN];
#pragma unroll
        for (int o4 = 0; o4 < 16; o4++) {
            float4 r;
            r.x = fmaxf(acc[4 * o4 + 0], 0.f);
            r.y = fmaxf(acc[4 * o4 + 1], 0.f);
            r.z = fmaxf(acc[4 * o4 + 2], 0.f);
            r.w = fmaxf(acc[4 * o4 + 3], 0.f);
            dst[o4] = r;
        }
    }
}

// ---------------- edge kernel (FFMA2 path) ----------------
#define WPB 4      // warps per block
#define EPT 32     // edges per warp-tile
#define GP  36     // sGT row pitch (floats): 16B-aligned rows, conflict-free col writes
#define TP  66     // KN1 tile pitch (floats): 8B-aligned float2 rows
#define SM_TP (64 * TP)
#define SM_GT (64 * GP)

__global__ void __launch_bounds__(WPB * 32)
edge_kernel(const int* __restrict__ iInd, const int* __restrict__ jInd,
            const float* __restrict__ KN1w, int nE) {
    extern __shared__ float sm[];
    float* sTp = sm;                         // sTp[k*TP+o] = KN1[o][k]
    float* sT2 = sm + SM_TP;                 // sT2[a*TP+b] = KN1[a][b]
    float* sGTall = sm + 2 * SM_TP;          // WPB * (64 x GP), k-major g tiles
    float* sWall  = sGTall + WPB * SM_GT;
    int*   sIall  = (int*)(sWall + WPB * EPT);
    int*   sJall  = sIall + WPB * EPT;

    for (int idx = threadIdx.x; idx < 64 * 64; idx += blockDim.x) {
        int o = idx >> 6, k = idx & 63;
        float v = KN1w[idx];                 // KN1[o][k]
        sTp[k * TP + o] = v;
        sT2[o * TP + k] = v;                 // sT2[a*TP+b] = KN1[a][b]
    }
    __syncthreads();

    int lane = threadIdx.x & 31;
    int ws   = threadIdx.x >> 5;
    float* gt = sGTall + ws * SM_GT;
    float* sW = sWall + ws * EPT;
    int*   sI = sIall + ws * EPT;
    int*   sJ = sJall + ws * EPT;
    int o0 = 2 * lane;

    long long gwarp = (long long)blockIdx.x * WPB + ws;
    long long nwarp = (long long)gridDim.x * WPB;

    for (long long base = gwarp * EPT; base < nE; base += nwarp * EPT) {
        // ---- gather: lane = edge; write g k-major (conflict-free) ----
        long long e = base + lane;
        int I = 0, J = 0; float w = 0.f;
        if (e < (long long)nE) { I = iInd[e]; J = jInd[e]; w = g_dinv[I] * g_dinv[J]; }
        sI[lane] = I; sJ[lane] = J; sW[lane] = w;
        const float4* xi = (const float4*)&g_x[(size_t)I * NOPEN];
        const float4* xj = (const float4*)&g_x[(size_t)J * NOPEN];
#pragma unroll
        for (int kk = 0; kk < 16; kk++) {
            float4 a = xi[kk], b = xj[kk];
            gt[(4 * kk + 0) * GP + lane] = (a.x - b.x) * w;
            gt[(4 * kk + 1) * GP + lane] = (a.y - b.y) * w;
            gt[(4 * kk + 2) * GP + lane] = (a.z - b.z) * w;
            gt[(4 * kk + 3) * GP + lane] = (a.w - b.w) * w;
        }
        __syncwarp();

        // ---- two halves of 16 edges ----
#pragma unroll
        for (int h = 0; h < 2; h++) {
            const int c0 = h * 16;
            unsigned long long acc0[8], acc1[8];
#pragma unroll
            for (int p = 0; p < 8; p++) { acc0[p] = 0ull; acc1[p] = 0ull; }

            // matvec1: z[o][c] = sum_k KN1[o][k] * g[k][c]
#pragma unroll 4
            for (int k = 0; k < 64; k++) {
                float2 av = *(const float2*)&sTp[k * TP + o0];
                unsigned long long a0 = dup2(av.x), a1 = dup2(av.y);
                const ulonglong2* gr = (const ulonglong2*)&gt[k * GP + c0];
                ulonglong2 q0 = gr[0], q1 = gr[1], q2 = gr[2], q3 = gr[3];
                acc0[0] = ffma2(a0, q0.x, acc0[0]); acc1[0] = ffma2(a1, q0.x, acc1[0]);
                acc0[1] = ffma2(a0, q0.y, acc0[1]); acc1[1] = ffma2(a1, q0.y, acc1[1]);
                acc0[2] = ffma2(a0, q1.x, acc0[2]); acc1[2] = ffma2(a1, q1.x, acc1[2]);
                acc0[3] = ffma2(a0, q1.y, acc0[3]); acc1[3] = ffma2(a1, q1.y, acc1[3]);
                acc0[4] = ffma2(a0, q2.x, acc0[4]); acc1[4] = ffma2(a1, q2.x, acc1[4]);
                acc0[5] = ffma2(a0, q2.y, acc0[5]); acc1[5] = ffma2(a1, q2.y, acc1[5]);
                acc0[6] = ffma2(a0, q3.x, acc0[6]); acc1[6] = ffma2(a1, q3.x, acc1[6]);
                acc0[7] = ffma2(a0, q3.y, acc0[7]); acc1[7] = ffma2(a1, q3.y, acc1[7]);
            }
            __syncwarp();   // all reads of g columns c0..c0+15 done

            // relu + store z back into same columns (k-major rows o)
#pragma unroll
            for (int p = 0; p < 8; p++) {
                float2 v0 = unpk(acc0[p]), v1 = unpk(acc1[p]);
                *(unsigned long long*)&gt[(o0)     * GP + c0 + 2 * p] =
                    pk(fmaxf(v0.x, 0.f), fmaxf(v0.y, 0.f));
                *(unsigned long long*)&gt[(o0 + 1) * GP + c0 + 2 * p] =
                    pk(fmaxf(v1.x, 0.f), fmaxf(v1.y, 0.f));
            }
            __syncwarp();   // z visible to whole warp

            // matvec2: y[o][c] = sum_k KN1[k][o] * z[k][c]
#pragma unroll
            for (int p = 0; p < 8; p++) { acc0[p] = 0ull; acc1[p] = 0ull; }
#pragma unroll 4
            for (int k = 0; k < 64; k++) {
                float2 av = *(const float2*)&sT2[k * TP + o0];   // (KN1[k][o0], KN1[k][o1])
                unsigned long long a0 = dup2(av.x), a1 = dup2(av.y);
                const ulonglong2* gr = (const ulonglong2*)&gt[k * GP + c0];
                ulonglong2 q0 = gr[0], q1 = gr[1], q2 = gr[2], q3 = gr[3];
                acc0[0] = ffma2(a0, q0.x, acc0[0]); acc1[0] = ffma2(a1, q0.x, acc1[0]);
                acc0[1] = ffma2(a0, q0.y, acc0[1]); acc1[1] = ffma2(a1, q0.y, acc1[1]);
                acc0[2] = ffma2(a0, q1.x, acc0[2]); acc1[2] = ffma2(a1, q1.x, acc1[2]);
                acc0[3] = ffma2(a0, q1.y, acc0[3]); acc1[3] = ffma2(a1, q1.y, acc1[3]);
                acc0[4] = ffma2(a0, q2.x, acc0[4]); acc1[4] = ffma2(a1, q2.x, acc1[4]);
                acc0[5] = ffma2(a0, q2.y, acc0[5]); acc1[5] = ffma2(a1, q2.y, acc1[5]);
                acc0[6] = ffma2(a0, q3.x, acc0[6]); acc1[6] = ffma2(a1, q3.x, acc1[6]);
                acc0[7] = ffma2(a0, q3.y, acc0[7]); acc1[7] = ffma2(a1, q3.y, acc1[7]);
            }

            // scatter: div[I] += w*y ; div[J] -= w*y
#pragma unroll
            for (int p = 0; p < 8; p++) {
                int c = c0 + 2 * p;
                float2 ya = unpk(acc0[p]);   // y[o0][c], y[o0][c+1]
                float2 yb = unpk(acc1[p]);   // y[o1][c], y[o1][c+1]
                {
                    int I1 = sI[c], J1 = sJ[c]; float w1 = sW[c];
                    float u0 = ya.x * w1, u1 = yb.x * w1;
                    asm volatile("red.global.add.v2.f32 [%0], {%1,%2};"
                                 :: "l"(&g_div[(size_t)I1 * NOPEN + o0]),
                                    "f"(u0), "f"(u1) : "memory");
                    asm volatile("red.global.add.v2.f32 [%0], {%1,%2};"
                                 :: "l"(&g_div[(size_t)J1 * NOPEN + o0]),
                                    "f"(-u0), "f"(-u1) : "memory");
                }
                {
                    int I2 = sI[c + 1], J2 = sJ[c + 1]; float w2 = sW[c + 1];
                    float u0 = ya.y * w2, u1 = yb.y * w2;
                    asm volatile("red.global.add.v2.f32 [%0], {%1,%2};"
                                 :: "l"(&g_div[(size_t)I2 * NOPEN + o0]),
                                    "f"(u0), "f"(u1) : "memory");
                    asm volatile("red.global.add.v2.f32 [%0], {%1,%2};"
                                 :: "l"(&g_div[(size_t)J2 * NOPEN + o0]),
                                    "f"(-u0), "f"(-u1) : "memory");
                }
            }
            __syncwarp();   // protect gt/sI/sJ/sW before next half/tile
        }
    }
}

// ---------------- x -= dt*H*div ; div = 0 (vectorized) ----------------
__global__ void update_kernel(int total4) {
    int i = blockIdx.x * blockDim.x + threadIdx.x;
    if (i < total4) {
        float4 x = ((float4*)g_x)[i];
        float4 d = ((float4*)g_div)[i];
        x.x -= DTH * d.x; x.y -= DTH * d.y; x.z -= DTH * d.z; x.w -= DTH * d.w;
        ((float4*)g_x)[i] = x;
        ((float4*)g_div)[i] = make_float4(0.f, 0.f, 0.f, 0.f);
    }
}

// ---------------- out = log_softmax(KNclose @ x) ----------------
__global__ void final_kernel(const float* __restrict__ KC, float* __restrict__ out,
                             int nN) {
    __shared__ float sC[64 * 65];            // sC[i*65+o] = KC[o][i]
    __shared__ __align__(16) float sX[8][64];
    for (int idx = threadIdx.x; idx < 64 * 64; idx += blockDim.x) {
        int o = idx >> 6, i = idx & 63;
        sC[i * 65 + o] = KC[idx];
    }
    __syncthreads();

    int lane  = threadIdx.x & 31;
    int ws    = threadIdx.x >> 5;
    int warp  = (blockIdx.x * blockDim.x + threadIdx.x) >> 5;
    int nwarp = (gridDim.x * blockDim.x) >> 5;
    int o0 = 2 * lane;

    for (int n = warp; n < nN; n += nwarp) {
        *(float2*)&sX[ws][o0] = *(const float2*)&g_x[(size_t)n * NOPEN + o0];
        __syncwarp();
        float v0 = 0.f, v1 = 0.f;
#pragma unroll 8
        for (int i = 0; i < 64; i++) {
            float xi = sX[ws][i];
            v0 += sC[i * 65 + o0] * xi;
            v1 += sC[i * 65 + o0 + 1] * xi;
        }
        float m = fmaxf(v0, v1);
#pragma unroll
        for (int off = 16; off; off >>= 1)
            m = fmaxf(m, __shfl_xor_sync(0xffffffffu, m, off));
        float s = expf(v0 - m) + expf(v1 - m);
#pragma unroll
        for (int off = 16; off; off >>= 1)
            s += __shfl_xor_sync(0xffffffffu, s, off);
        float lse = m + logf(s);
        float2 r;
        r.x = v0 - lse;
        r.y = v1 - lse;
        *(float2*)&out[(size_t)n * NOPEN + o0] = r;
        __syncwarp();
    }
}

// ---------------- launch ----------------
#define EDGE_SMEM ((2 * SM_TP + WPB * SM_GT + WPB * EPT) * 4 + WPB * EPT * 8)

extern "C" void kernel_launch(void* const* d_in, const int* in_sizes, int n_in,
                              void* d_out, int out_size) {
    const float* xn   = (const float*)d_in[0];
    const int*   iInd = (const int*)d_in[1];
    const int*   jInd = (const int*)d_in[2];
    int base = 3;
    if (n_in >= 7 && in_sizes[3] == 1) base = 4;
    const float* K1  = (const float*)d_in[base];
    const float* KN1 = (const float*)d_in[base + 1];
    const float* KC  = (const float*)d_in[base + 2];

    int nN = in_sizes[0] / NNIN;
    int nE = in_sizes[1];

    cudaFuncSetAttribute(edge_kernel,
                         cudaFuncAttributeMaxDynamicSharedMemorySize, EDGE_SMEM);

    deg_init_kernel<<<(nN + 255) / 256, 256>>>(nN);
    deg_count_kernel<<<(nE + 255) / 256, 256>>>(jInd, nE);
    dinv_kernel<<<(nN + 255) / 256, 256>>>(nN);
    x0_kernel<<<(nN + 255) / 256, 256>>>(xn, K1, nN);

    int total4 = nN * NOPEN / 4;
    for (int l = 0; l < 4; l++) {
        edge_kernel<<<444, WPB * 32, EDGE_SMEM>>>(iInd, jInd, KN1, nE);
        update_kernel<<<(total4 + 255) / 256, 256>>>(total4);
    }
    final_kernel<<<1024, 256>>>(KC, (float*)d_out, nN);
}

// round 3
// speedup vs baseline: 3.7419x; 3.7419x over previous
#include <cuda_runtime.h>
#include <cuda_bf16.h>
#include <math.h>

// ---------------- problem constants ----------------
#define NOPEN 64
#define NNIN  16
#define MAXN  65536
#define DTH   0.025f           // dt*H = (1/4)*0.1

// ---------------- device scratch ----------------
__device__ float g_x[(size_t)MAXN * NOPEN];   // node features
__device__ float g_p[(size_t)MAXN * NOPEN];   // p = KN1 @ x
__device__ float g_s[(size_t)MAXN * NOPEN];   // edge aggregate (kept zeroed)
__device__ float g_dinv[MAXN];
__device__ int   g_deg[MAXN];

// ---------------- degree / norm ----------------
__global__ void deg_init_kernel(int nN) {
    int i = blockIdx.x * blockDim.x + threadIdx.x;
    if (i < nN) g_deg[i] = 1;
}
__global__ void deg_count_kernel(const int* __restrict__ jInd, int nE) {
    int i = blockIdx.x * blockDim.x + threadIdx.x;
    if (i < nE) atomicAdd(&g_deg[jInd[i]], 1);
}
__global__ void dinv_kernel(int nN) {
    int i = blockIdx.x * blockDim.x + threadIdx.x;
    if (i < nN) g_dinv[i] = rsqrtf((float)g_deg[i]);
}

// ---------------- x0 = relu(K1Nopen @ xn), block-tiled, 2 output passes ----
__global__ void __launch_bounds__(256)
x0_kernel(const float* __restrict__ xn, const float* __restrict__ K1, int nN) {
    __shared__ float sK[NNIN * NOPEN];       // sK[c*64+o] = K1[o][c]
    __shared__ float sX[NNIN][256];
    for (int idx = threadIdx.x; idx < NOPEN * NNIN; idx += blockDim.x) {
        int o = idx >> 4, c = idx & 15;
        sK[c * NOPEN + o] = K1[idx];
    }
    int n0 = blockIdx.x * 256;
    for (int idx = threadIdx.x; idx < NNIN * 256; idx += blockDim.x) {
        int c = idx >> 8, nn = idx & 255;
        int n = n0 + nn;
        sX[c][nn] = (n < nN) ? xn[(size_t)c * nN + n] : 0.f;
    }
    __syncthreads();

    int n = n0 + threadIdx.x;
    if (n >= nN) return;
    float* dst = &g_x[(size_t)n * NOPEN];
#pragma unroll
    for (int half = 0; half < 2; half++) {
        float acc[32];
#pragma unroll
        for (int o = 0; o < 32; o++) acc[o] = 0.f;
#pragma unroll
        for (int c = 0; c < NNIN; c++) {
            float xc = sX[c][threadIdx.x];
#pragma unroll
            for (int o = 0; o < 32; o++)
                acc[o] += sK[c * NOPEN + half * 32 + o] * xc;
        }
#pragma unroll
        for (int o4 = 0; o4 < 8; o4++) {
            float4 r;
            r.x = fmaxf(acc[4 * o4 + 0], 0.f);
            r.y = fmaxf(acc[4 * o4 + 1], 0.f);
            r.z = fmaxf(acc[4 * o4 + 2], 0.f);
            r.w = fmaxf(acc[4 * o4 + 3], 0.f);
            ((float4*)dst)[half * 8 + o4] = r;
        }
    }
}

// ---------------- pre: p = KN1 @ x (warp per node) ----------------
__global__ void __launch_bounds__(256)
pre_kernel(const float* __restrict__ KN1w, int nN) {
    __shared__ float sKp[64 * 66];           // sKp[k*66+o] = KN1[o][k]
    __shared__ float sRow[8][64];
    for (int idx = threadIdx.x; idx < 64 * 64; idx += blockDim.x) {
        int r = idx >> 6, c = idx & 63;      // KN1[r][c]
        sKp[c * 66 + r] = KN1w[idx];
    }
    __syncthreads();

    int lane = threadIdx.x & 31;
    int ws   = threadIdx.x >> 5;
    int n    = blockIdx.x * 8 + ws;
    if (n >= nN) return;
    int o0 = 2 * lane;

    float2 xv = *(const float2*)&g_x[(size_t)n * NOPEN + o0];
    sRow[ws][o0] = xv.x; sRow[ws][o0 + 1] = xv.y;
    __syncwarp();
    float p0 = 0.f, p1 = 0.f;
#pragma unroll 8
    for (int k = 0; k < 64; k++) {
        float xk = sRow[ws][k];
        float2 a = *(const float2*)&sKp[k * 66 + o0];
        p0 += a.x * xk;
        p1 += a.y * xk;
    }
    float2 r; r.x = p0; r.y = p1;
    *(float2*)&g_p[(size_t)n * NOPEN + o0] = r;
}

// ---------------- edge kernel: s[I] += w^2*relu(pI-pJ); s[J] -= ... --------
__global__ void __launch_bounds__(256)
edge_kernel(const int* __restrict__ iInd, const int* __restrict__ jInd, int nE) {
    int lane = threadIdx.x & 31;
    long long warp = (long long)blockIdx.x * 8 + (threadIdx.x >> 5);
    long long base = warp * 32;
    if (base >= nE) return;

    int e = (int)base + lane;
    int I = 0, J = 0; float w2 = 0.f;
    if (e < nE) {
        I = iInd[e]; J = jInd[e];
        float w = g_dinv[I] * g_dinv[J];
        w2 = w * w;
    }
    int o0 = 2 * lane;
    int cnt = nE - (int)base;
    if (cnt > 32) cnt = 32;

#pragma unroll 4
    for (int c = 0; c < 32; c++) {
        if (c >= cnt) break;
        int   Ic = __shfl_sync(0xffffffffu, I, c);
        int   Jc = __shfl_sync(0xffffffffu, J, c);
        float wc = __shfl_sync(0xffffffffu, w2, c);
        float2 a = *(const float2*)&g_p[(size_t)Ic * NOPEN + o0];
        float2 b = *(const float2*)&g_p[(size_t)Jc * NOPEN + o0];
        float u0 = fmaxf(a.x - b.x, 0.f) * wc;
        float u1 = fmaxf(a.y - b.y, 0.f) * wc;
        asm volatile("red.global.add.v2.f32 [%0], {%1,%2};"
                     :: "l"(&g_s[(size_t)Ic * NOPEN + o0]), "f"(u0), "f"(u1)
                     : "memory");
        asm volatile("red.global.add.v2.f32 [%0], {%1,%2};"
                     :: "l"(&g_s[(size_t)Jc * NOPEN + o0]), "f"(-u0), "f"(-u1)
                     : "memory");
    }
}

// ---------------- update: x -= DTH * KN1^T @ s ; s = 0 ; [p = KN1 @ x] -----
__global__ void __launch_bounds__(256)
update_kernel(const float* __restrict__ KN1w, int nN, int computeP) {
    __shared__ float sKy[64 * 66];           // sKy[k*66+o] = KN1[k][o]
    __shared__ float sKp[64 * 66];           // sKp[k*66+o] = KN1[o][k]
    __shared__ float sRow[8][64];
    for (int idx = threadIdx.x; idx < 64 * 64; idx += blockDim.x) {
        int r = idx >> 6, c = idx & 63;      // KN1[r][c]
        float v = KN1w[idx];
        sKy[r * 66 + c] = v;
        sKp[c * 66 + r] = v;
    }
    __syncthreads();

    int lane = threadIdx.x & 31;
    int ws   = threadIdx.x >> 5;
    int n    = blockIdx.x * 8 + ws;
    if (n >= nN) return;
    int o0 = 2 * lane;
    size_t off = (size_t)n * NOPEN + o0;

    float2 s2 = *(const float2*)&g_s[off];
    *(float2*)&g_s[off] = make_float2(0.f, 0.f);
    sRow[ws][o0] = s2.x; sRow[ws][o0 + 1] = s2.y;
    __syncwarp();

    float y0 = 0.f, y1 = 0.f;
#pragma unroll 8
    for (int k = 0; k < 64; k++) {
        float sk = sRow[ws][k];
        float2 a = *(const float2*)&sKy[k * 66 + o0];
        y0 += a.x * sk;
        y1 += a.y * sk;
    }
    float2 xv = *(const float2*)&g_x[off];
    xv.x -= DTH * y0;
    xv.y -= DTH * y1;
    *(float2*)&g_x[off] = xv;

    if (computeP) {
        __syncwarp();
        sRow[ws][o0] = xv.x; sRow[ws][o0 + 1] = xv.y;
        __syncwarp();
        float p0 = 0.f, p1 = 0.f;
#pragma unroll 8
        for (int k = 0; k < 64; k++) {
            float xk = sRow[ws][k];
            float2 a = *(const float2*)&sKp[k * 66 + o0];
            p0 += a.x * xk;
            p1 += a.y * xk;
        }
        float2 r; r.x = p0; r.y = p1;
        *(float2*)&g_p[off] = r;
    }
}

// ---------------- out = log_softmax(KNclose @ x) ----------------
__global__ void __launch_bounds__(256)
final_kernel(const float* __restrict__ KC, float* __restrict__ out, int nN) {
    __shared__ float sC[64 * 66];            // sC[i*66+o] = KC[o][i]
    __shared__ float sX[8][64];
    for (int idx = threadIdx.x; idx < 64 * 64; idx += blockDim.x) {
        int o = idx >> 6, i = idx & 63;
        sC[i * 66 + o] = KC[idx];
    }
    __syncthreads();

    int lane = threadIdx.x & 31;
    int ws   = threadIdx.x >> 5;
    int n    = blockIdx.x * 8 + ws;
    if (n >= nN) return;
    int o0 = 2 * lane;

    float2 xv = *(const float2*)&g_x[(size_t)n * NOPEN + o0];
    sX[ws][o0] = xv.x; sX[ws][o0 + 1] = xv.y;
    __syncwarp();
    float v0 = 0.f, v1 = 0.f;
#pragma unroll 8
    for (int i = 0; i < 64; i++) {
        float xi = sX[ws][i];
        float2 a = *(const float2*)&sC[i * 66 + o0];
        v0 += a.x * xi;
        v1 += a.y * xi;
    }
    float m = fmaxf(v0, v1);
#pragma unroll
    for (int off = 16; off; off >>= 1)
        m = fmaxf(m, __shfl_xor_sync(0xffffffffu, m, off));
    float s = expf(v0 - m) + expf(v1 - m);
#pragma unroll
    for (int off = 16; off; off >>= 1)
        s += __shfl_xor_sync(0xffffffffu, s, off);
    float lse = m + logf(s);
    float2 r;
    r.x = v0 - lse;
    r.y = v1 - lse;
    *(float2*)&out[(size_t)n * NOPEN + o0] = r;
}

// ---------------- launch ----------------
extern "C" void kernel_launch(void* const* d_in, const int* in_sizes, int n_in,
                              void* d_out, int out_size) {
    const float* xn   = (const float*)d_in[0];
    const int*   iInd = (const int*)d_in[1];
    const int*   jInd = (const int*)d_in[2];
    int base = 3;
    if (n_in >= 7 && in_sizes[3] == 1) base = 4;
    const float* K1  = (const float*)d_in[base];
    const float* KN1 = (const float*)d_in[base + 1];
    const float* KC  = (const float*)d_in[base + 2];

    int nN = in_sizes[0] / NNIN;
    int nE = in_sizes[1];

    int nodeBlocks = (nN + 7) / 8;                 // warp per node, 8 warps/block
    long long tiles = ((long long)nE + 31) / 32;
    int edgeBlocks = (int)((tiles + 7) / 8);

    deg_init_kernel<<<(nN + 255) / 256, 256>>>(nN);
    deg_count_kernel<<<(nE + 255) / 256, 256>>>(jInd, nE);
    dinv_kernel<<<(nN + 255) / 256, 256>>>(nN);
    x0_kernel<<<(nN + 255) / 256, 256>>>(xn, K1, nN);
    pre_kernel<<<nodeBlocks, 256>>>(KN1, nN);

    for (int l = 0; l < 4; l++) {
        edge_kernel<<<edgeBlocks, 256>>>(iInd, jInd, nE);
        update_kernel<<<nodeBlocks, 256>>>(KN1, nN, l < 3 ? 1 : 0);
    }
    final_kernel<<<nodeBlocks, 256>>>(KC, (float*)d_out, nN);
}

// round 4
// speedup vs baseline: 3.9178x; 1.0470x over previous
#include <cuda_runtime.h>
#include <cuda_fp16.h>
#include <math.h>

// ---------------- problem constants ----------------
#define NOPEN 64
#define NNIN  16
#define MAXN  65536
#define DTH   0.025f           // dt*H = (1/4)*0.1

// ---------------- device scratch ----------------
__device__ float   g_x[(size_t)MAXN * NOPEN];   // node features (f32)
__device__ __half2 g_p[(size_t)MAXN * 32];      // p = KN1 @ x, f16, 32 half2/node
__device__ float   g_s[(size_t)MAXN * NOPEN];   // edge aggregate (kept zeroed)
__device__ float   g_dinv[MAXN];
__device__ int     g_deg[MAXN];

// ---------------- degree / norm ----------------
__global__ void deg_init_kernel(int nN) {
    int i = blockIdx.x * blockDim.x + threadIdx.x;
    if (i < nN) g_deg[i] = 1;
}
__global__ void deg_count_kernel(const int* __restrict__ jInd, int nE) {
    int i = blockIdx.x * blockDim.x + threadIdx.x;
    if (i < nE) atomicAdd(&g_deg[jInd[i]], 1);
}
__global__ void dinv_kernel(int nN) {
    int i = blockIdx.x * blockDim.x + threadIdx.x;
    if (i < nN) g_dinv[i] = rsqrtf((float)g_deg[i]);
}

// ---------------- x0 = relu(K1Nopen @ xn), block-tiled ----------------
__global__ void __launch_bounds__(256)
x0_kernel(const float* __restrict__ xn, const float* __restrict__ K1, int nN) {
    __shared__ float sK[NNIN * NOPEN];       // sK[c*64+o] = K1[o][c]
    __shared__ float sX[NNIN][256];
    for (int idx = threadIdx.x; idx < NOPEN * NNIN; idx += blockDim.x) {
        int o = idx >> 4, c = idx & 15;
        sK[c * NOPEN + o] = K1[idx];
    }
    int n0 = blockIdx.x * 256;
    for (int idx = threadIdx.x; idx < NNIN * 256; idx += blockDim.x) {
        int c = idx >> 8, nn = idx & 255;
        int n = n0 + nn;
        sX[c][nn] = (n < nN) ? xn[(size_t)c * nN + n] : 0.f;
    }
    __syncthreads();

    int n = n0 + threadIdx.x;
    if (n >= nN) return;
    float* dst = &g_x[(size_t)n * NOPEN];
#pragma unroll
    for (int half = 0; half < 2; half++) {
        float acc[32];
#pragma unroll
        for (int o = 0; o < 32; o++) acc[o] = 0.f;
#pragma unroll
        for (int c = 0; c < NNIN; c++) {
            float xc = sX[c][threadIdx.x];
#pragma unroll
            for (int o = 0; o < 32; o++)
                acc[o] += sK[c * NOPEN + half * 32 + o] * xc;
        }
#pragma unroll
        for (int o4 = 0; o4 < 8; o4++) {
            float4 r;
            r.x = fmaxf(acc[4 * o4 + 0], 0.f);
            r.y = fmaxf(acc[4 * o4 + 1], 0.f);
            r.z = fmaxf(acc[4 * o4 + 2], 0.f);
            r.w = fmaxf(acc[4 * o4 + 3], 0.f);
            ((float4*)dst)[half * 8 + o4] = r;
        }
    }
}

// ---------------- pre: p = f16(KN1 @ x) (warp per node) ----------------
__global__ void __launch_bounds__(256)
pre_kernel(const float* __restrict__ KN1w, int nN) {
    __shared__ float sKp[64 * 66];           // sKp[k*66+o] = KN1[o][k]
    __shared__ float sRow[8][64];
    for (int idx = threadIdx.x; idx < 64 * 64; idx += blockDim.x) {
        int r = idx >> 6, c = idx & 63;
        sKp[c * 66 + r] = KN1w[idx];
    }
    __syncthreads();

    int lane = threadIdx.x & 31;
    int ws   = threadIdx.x >> 5;
    int n    = blockIdx.x * 8 + ws;
    if (n >= nN) return;
    int o0 = 2 * lane;

    float2 xv = *(const float2*)&g_x[(size_t)n * NOPEN + o0];
    sRow[ws][o0] = xv.x; sRow[ws][o0 + 1] = xv.y;
    __syncwarp();
    float p0 = 0.f, p1 = 0.f;
#pragma unroll 8
    for (int k = 0; k < 64; k++) {
        float xk = sRow[ws][k];
        float2 a = *(const float2*)&sKp[k * 66 + o0];
        p0 += a.x * xk;
        p1 += a.y * xk;
    }
    g_p[(size_t)n * 32 + lane] = __floats2half2_rn(p0, p1);
}

// ---------------- edge kernel: s[I] += w^2*relu(pI-pJ); s[J] -= ... --------
__global__ void __launch_bounds__(256)
edge_kernel(const int* __restrict__ iInd, const int* __restrict__ jInd, int nE) {
    int lane = threadIdx.x & 31;
    long long warp = (long long)blockIdx.x * 8 + (threadIdx.x >> 5);
    long long base = warp * 32;
    if (base >= nE) return;

    int e = (int)base + lane;
    int I = 0, J = 0; float w2 = 0.f;
    if (e < nE) {
        I = iInd[e]; J = jInd[e];
        float w = g_dinv[I] * g_dinv[J];
        w2 = w * w;
    }
    int o0 = 2 * lane;
    int cnt = nE - (int)base;
    if (cnt > 32) cnt = 32;

#pragma unroll 4
    for (int c = 0; c < 32; c++) {
        if (c >= cnt) break;
        int   Ic = __shfl_sync(0xffffffffu, I, c);
        int   Jc = __shfl_sync(0xffffffffu, J, c);
        float wc = __shfl_sync(0xffffffffu, w2, c);
        float2 a = __half22float2(g_p[(size_t)Ic * 32 + lane]);
        float2 b = __half22float2(g_p[(size_t)Jc * 32 + lane]);
        float u0 = fmaxf(a.x - b.x, 0.f) * wc;
        float u1 = fmaxf(a.y - b.y, 0.f) * wc;
        asm volatile("red.global.add.v2.f32 [%0], {%1,%2};"
                     :: "l"(&g_s[(size_t)Ic * NOPEN + o0]), "f"(u0), "f"(u1)
                     : "memory");
        asm volatile("red.global.add.v2.f32 [%0], {%1,%2};"
                     :: "l"(&g_s[(size_t)Jc * NOPEN + o0]), "f"(-u0), "f"(-u1)
                     : "memory");
    }
}

// ---------------- update: x -= DTH * KN1^T @ s ; s = 0 ; [p = f16(KN1@x)] --
__global__ void __launch_bounds__(256)
update_kernel(const float* __restrict__ KN1w, int nN, int computeP) {
    __shared__ float sKy[64 * 66];           // sKy[k*66+o] = KN1[k][o]
    __shared__ float sKp[64 * 66];           // sKp[k*66+o] = KN1[o][k]
    __shared__ float sRow[8][64];
    for (int idx = threadIdx.x; idx < 64 * 64; idx += blockDim.x) {
        int r = idx >> 6, c = idx & 63;
        float v = KN1w[idx];
        sKy[r * 66 + c] = v;
        sKp[c * 66 + r] = v;
    }
    __syncthreads();

    int lane = threadIdx.x & 31;
    int ws   = threadIdx.x >> 5;
    int n    = blockIdx.x * 8 + ws;
    if (n >= nN) return;
    int o0 = 2 * lane;
    size_t off = (size_t)n * NOPEN + o0;

    float2 s2 = *(const float2*)&g_s[off];
    *(float2*)&g_s[off] = make_float2(0.f, 0.f);
    sRow[ws][o0] = s2.x; sRow[ws][o0 + 1] = s2.y;
    __syncwarp();

    float y0 = 0.f, y1 = 0.f;
#pragma unroll 8
    for (int k = 0; k < 64; k++) {
        float sk = sRow[ws][k];
        float2 a = *(const float2*)&sKy[k * 66 + o0];
        y0 += a.x * sk;
        y1 += a.y * sk;
    }
    float2 xv = *(const float2*)&g_x[off];
    xv.x -= DTH * y0;
    xv.y -= DTH * y1;
    *(float2*)&g_x[off] = xv;

    if (computeP) {
        __syncwarp();
        sRow[ws][o0] = xv.x; sRow[ws][o0 + 1] = xv.y;
        __syncwarp();
        float p0 = 0.f, p1 = 0.f;
#pragma unroll 8
        for (int k = 0; k < 64; k++) {
            float xk = sRow[ws][k];
            float2 a = *(const float2*)&sKp[k * 66 + o0];
            p0 += a.x * xk;
            p1 += a.y * xk;
        }
        g_p[(size_t)n * 32 + lane] = __floats2half2_rn(p0, p1);
    }
}

// ---------------- out = log_softmax(KNclose @ x) ----------------
__global__ void __launch_bounds__(256)
final_kernel(const float* __restrict__ KC, float* __restrict__ out, int nN) {
    __shared__ float sC[64 * 66];            // sC[i*66+o] = KC[o][i]
    __shared__ float sX[8][64];
    for (int idx = threadIdx.x; idx < 64 * 64; idx += blockDim.x) {
        int o = idx >> 6, i = idx & 63;
        sC[i * 66 + o] = KC[idx];
    }
    __syncthreads();

    int lane = threadIdx.x & 31;
    int ws   = threadIdx.x >> 5;
    int n    = blockIdx.x * 8 + ws;
    if (n >= nN) return;
    int o0 = 2 * lane;

    float2 xv = *(const float2*)&g_x[(size_t)n * NOPEN + o0];
    sX[ws][o0] = xv.x; sX[ws][o0 + 1] = xv.y;
    __syncwarp();
    float v0 = 0.f, v1 = 0.f;
#pragma unroll 8
    for (int i = 0; i < 64; i++) {
        float xi = sX[ws][i];
        float2 a = *(const float2*)&sC[i * 66 + o0];
        v0 += a.x * xi;
        v1 += a.y * xi;
    }
    float m = fmaxf(v0, v1);
#pragma unroll
    for (int off = 16; off; off >>= 1)
        m = fmaxf(m, __shfl_xor_sync(0xffffffffu, m, off));
    float s = expf(v0 - m) + expf(v1 - m);
#pragma unroll
    for (int off = 16; off; off >>= 1)
        s += __shfl_xor_sync(0xffffffffu, s, off);
    float lse = m + logf(s);
    float2 r;
    r.x = v0 - lse;
    r.y = v1 - lse;
    *(float2*)&out[(size_t)n * NOPEN + o0] = r;
}

// ---------------- launch ----------------
extern "C" void kernel_launch(void* const* d_in, const int* in_sizes, int n_in,
                              void* d_out, int out_size) {
    const float* xn   = (const float*)d_in[0];
    const int*   iInd = (const int*)d_in[1];
    const int*   jInd = (const int*)d_in[2];
    int base = 3;
    if (n_in >= 7 && in_sizes[3] == 1) base = 4;
    const float* K1  = (const float*)d_in[base];
    const float* KN1 = (const float*)d_in[base + 1];
    const float* KC  = (const float*)d_in[base + 2];

    int nN = in_sizes[0] / NNIN;
    int nE = in_sizes[1];

    int nodeBlocks = (nN + 7) / 8;
    long long tiles = ((long long)nE + 31) / 32;
    int edgeBlocks = (int)((tiles + 7) / 8);

    deg_init_kernel<<<(nN + 255) / 256, 256>>>(nN);
    deg_count_kernel<<<(nE + 255) / 256, 256>>>(jInd, nE);
    dinv_kernel<<<(nN + 255) / 256, 256>>>(nN);
    x0_kernel<<<(nN + 255) / 256, 256>>>(xn, K1, nN);
    pre_kernel<<<nodeBlocks, 256>>>(KN1, nN);

    for (int l = 0; l < 4; l++) {
        edge_kernel<<<edgeBlocks, 256>>>(iInd, jInd, nE);
        update_kernel<<<nodeBlocks, 256>>>(KN1, nN, l < 3 ? 1 : 0);
    }
    final_kernel<<<nodeBlocks, 256>>>(KC, (float*)d_out, nN);
}

// round 5
// speedup vs baseline: 5.2364x; 1.3366x over previous
#include <cuda_runtime.h>
#include <cuda_fp16.h>
#include <math.h>

// ---------------- problem constants ----------------
#define NOPEN 64
#define NNIN  16
#define MAXN  65536
#define DTH   0.025f           // dt*H = (1/4)*0.1

// ---------------- device scratch ----------------
__device__ float   g_x[(size_t)MAXN * NOPEN];   // node features (f32)
__device__ __half2 g_p[(size_t)MAXN * 32];      // p = KN1 @ x (f16), 32 half2/node
__device__ __half2 g_s[(size_t)MAXN * 32];      // edge aggregate (f16, kept zeroed)
__device__ float   g_dinv[MAXN];
__device__ int     g_deg[MAXN];

// ---------------- degree / norm ----------------
__global__ void deg_init_kernel(int nN) {
    int i = blockIdx.x * blockDim.x + threadIdx.x;
    if (i < nN) g_deg[i] = 1;
}
__global__ void deg_count_kernel(const int* __restrict__ jInd, int nE) {
    int i = blockIdx.x * blockDim.x + threadIdx.x;
    if (i < nE) atomicAdd(&g_deg[jInd[i]], 1);
}
__global__ void dinv_kernel(int nN) {
    int i = blockIdx.x * blockDim.x + threadIdx.x;
    if (i < nN) g_dinv[i] = rsqrtf((float)g_deg[i]);
}

// ---------------- x0 = relu(K1Nopen @ xn), block-tiled ----------------
__global__ void __launch_bounds__(256)
x0_kernel(const float* __restrict__ xn, const float* __restrict__ K1, int nN) {
    __shared__ float sK[NNIN * NOPEN];       // sK[c*64+o] = K1[o][c]
    __shared__ float sX[NNIN][256];
    for (int idx = threadIdx.x; idx < NOPEN * NNIN; idx += blockDim.x) {
        int o = idx >> 4, c = idx & 15;
        sK[c * NOPEN + o] = K1[idx];
    }
    int n0 = blockIdx.x * 256;
    for (int idx = threadIdx.x; idx < NNIN * 256; idx += blockDim.x) {
        int c = idx >> 8, nn = idx & 255;
        int n = n0 + nn;
        sX[c][nn] = (n < nN) ? xn[(size_t)c * nN + n] : 0.f;
    }
    __syncthreads();

    int n = n0 + threadIdx.x;
    if (n >= nN) return;
    float* dst = &g_x[(size_t)n * NOPEN];
#pragma unroll
    for (int half = 0; half < 2; half++) {
        float acc[32];
#pragma unroll
        for (int o = 0; o < 32; o++) acc[o] = 0.f;
#pragma unroll
        for (int c = 0; c < NNIN; c++) {
            float xc = sX[c][threadIdx.x];
#pragma unroll
            for (int o = 0; o < 32; o++)
                acc[o] += sK[c * NOPEN + half * 32 + o] * xc;
        }
#pragma unroll
        for (int o4 = 0; o4 < 8; o4++) {
            float4 r;
            r.x = fmaxf(acc[4 * o4 + 0], 0.f);
            r.y = fmaxf(acc[4 * o4 + 1], 0.f);
            r.z = fmaxf(acc[4 * o4 + 2], 0.f);
            r.w = fmaxf(acc[4 * o4 + 3], 0.f);
            ((float4*)dst)[half * 8 + o4] = r;
        }
    }
}

// ---------------- pre: p = f16(KN1 @ x) (warp per node) ----------------
__global__ void __launch_bounds__(256)
pre_kernel(const float* __restrict__ KN1w, int nN) {
    __shared__ float sKp[64 * 66];           // sKp[k*66+o] = KN1[o][k]
    __shared__ float sRow[8][64];
    for (int idx = threadIdx.x; idx < 64 * 64; idx += blockDim.x) {
        int r = idx >> 6, c = idx & 63;
        sKp[c * 66 + r] = KN1w[idx];
    }
    __syncthreads();

    int lane = threadIdx.x & 31;
    int ws   = threadIdx.x >> 5;
    int n    = blockIdx.x * 8 + ws;
    if (n >= nN) return;
    int o0 = 2 * lane;

    float2 xv = *(const float2*)&g_x[(size_t)n * NOPEN + o0];
    sRow[ws][o0] = xv.x; sRow[ws][o0 + 1] = xv.y;
    __syncwarp();
    float p0 = 0.f, p1 = 0.f;
#pragma unroll 8
    for (int k = 0; k < 64; k++) {
        float xk = sRow[ws][k];
        float2 a = *(const float2*)&sKp[k * 66 + o0];
        p0 += a.x * xk;
        p1 += a.y * xk;
    }
    g_p[(size_t)n * 32 + lane] = __floats2half2_rn(p0, p1);
}

// ---------------- edge kernel ----------------
// 2 edges per warp-iteration; lane = (edge-sel, dir, chunk).
// One red.v4.f16x2 instruction scatters BOTH directions of BOTH edges.
__global__ void __launch_bounds__(256)
edge_kernel(const int* __restrict__ iInd, const int* __restrict__ jInd, int nE) {
    int lane = threadIdx.x & 31;
    long long warp = (long long)blockIdx.x * 8 + (threadIdx.x >> 5);
    long long base = warp * 32;
    if (base >= nE) return;

    int e = (int)base + lane;
    int I = 0, J = 0; float w2 = 0.f;
    if (e < nE) {
        I = iInd[e]; J = jInd[e];
        float w = g_dinv[I] * g_dinv[J];
        w2 = w * w;                           // tail edges: w2 = 0 -> adds 0
    }

    int sub  = lane & 7;           // 16B chunk within the 128B node row
    int dir  = (lane >> 3) & 1;    // 0: +into I, 1: -into J
    int esel = lane >> 4;          // which of the 2 edges this half-warp owns
    const __half2 zero2 = __float2half2_rn(0.f);

#pragma unroll 4
    for (int c = 0; c < 16; c++) {
        int eidx = 2 * c + esel;
        int   Ic = __shfl_sync(0xffffffffu, I,  eidx);
        int   Jc = __shfl_sync(0xffffffffu, J,  eidx);
        float wc = __shfl_sync(0xffffffffu, w2, eidx);

        const uint4* ap = (const uint4*)&g_p[(size_t)Ic * 32 + sub * 4];
        const uint4* bp = (const uint4*)&g_p[(size_t)Jc * 32 + sub * 4];
        uint4 av = *ap, bv = *bp;

        __half2 wh = __float2half2_rn(dir ? -wc : wc);
        __half2 u0 = __hmul2(__hmax2(__hsub2(*(__half2*)&av.x, *(__half2*)&bv.x), zero2), wh);
        __half2 u1 = __hmul2(__hmax2(__hsub2(*(__half2*)&av.y, *(__half2*)&bv.y), zero2), wh);
        __half2 u2 = __hmul2(__hmax2(__hsub2(*(__half2*)&av.z, *(__half2*)&bv.z), zero2), wh);
        __half2 u3 = __hmul2(__hmax2(__hsub2(*(__half2*)&av.w, *(__half2*)&bv.w), zero2), wh);

        int T = dir ? Jc : Ic;
        __half2* dst = &g_s[(size_t)T * 32 + sub * 4];
        asm volatile("red.global.add.noftz.v4.f16x2 [%0], {%1,%2,%3,%4};"
                     :: "l"(dst),
                        "r"(*(unsigned*)&u0), "r"(*(unsigned*)&u1),
                        "r"(*(unsigned*)&u2), "r"(*(unsigned*)&u3)
                     : "memory");
    }
}

// ---------------- update: x -= DTH * KN1^T @ s ; s = 0 ; [p = f16(KN1@x)] --
__global__ void __launch_bounds__(256)
update_kernel(const float* __restrict__ KN1w, int nN, int computeP) {
    __shared__ float sKy[64 * 66];           // sKy[k*66+o] = KN1[k][o]
    __shared__ float sKp[64 * 66];           // sKp[k*66+o] = KN1[o][k]
    __shared__ float sRow[8][64];
    for (int idx = threadIdx.x; idx < 64 * 64; idx += blockDim.x) {
        int r = idx >> 6, c = idx & 63;
        float v = KN1w[idx];
        sKy[r * 66 + c] = v;
        sKp[c * 66 + r] = v;
    }
    __syncthreads();

    int lane = threadIdx.x & 31;
    int ws   = threadIdx.x >> 5;
    int n    = blockIdx.x * 8 + ws;
    if (n >= nN) return;
    int o0 = 2 * lane;
    size_t off = (size_t)n * NOPEN + o0;
    size_t hoff = (size_t)n * 32 + lane;

    float2 s2 = __half22float2(g_s[hoff]);
    g_s[hoff] = __float2half2_rn(0.f);
    sRow[ws][o0] = s2.x; sRow[ws][o0 + 1] = s2.y;
    __syncwarp();

    float y0 = 0.f, y1 = 0.f;
#pragma unroll 8
    for (int k = 0; k < 64; k++) {
        float sk = sRow[ws][k];
        float2 a = *(const float2*)&sKy[k * 66 + o0];
        y0 += a.x * sk;
        y1 += a.y * sk;
    }
    float2 xv = *(const float2*)&g_x[off];
    xv.x -= DTH * y0;
    xv.y -= DTH * y1;
    *(float2*)&g_x[off] = xv;

    if (computeP) {
        __syncwarp();
        sRow[ws][o0] = xv.x; sRow[ws][o0 + 1] = xv.y;
        __syncwarp();
        float p0 = 0.f, p1 = 0.f;
#pragma unroll 8
        for (int k = 0; k < 64; k++) {
            float xk = sRow[ws][k];
            float2 a = *(const float2*)&sKp[k * 66 + o0];
            p0 += a.x * xk;
            p1 += a.y * xk;
        }
        g_p[hoff] = __floats2half2_rn(p0, p1);
    }
}

// ---------------- out = log_softmax(KNclose @ x) ----------------
__global__ void __launch_bounds__(256)
final_kernel(const float* __restrict__ KC, float* __restrict__ out, int nN) {
    __shared__ float sC[64 * 66];            // sC[i*66+o] = KC[o][i]
    __shared__ float sX[8][64];
    for (int idx = threadIdx.x; idx < 64 * 64; idx += blockDim.x) {
        int o = idx >> 6, i = idx & 63;
        sC[i * 66 + o] = KC[idx];
    }
    __syncthreads();

    int lane = threadIdx.x & 31;
    int ws   = threadIdx.x >> 5;
    int n    = blockIdx.x * 8 + ws;
    if (n >= nN) return;
    int o0 = 2 * lane;

    float2 xv = *(const float2*)&g_x[(size_t)n * NOPEN + o0];
    sX[ws][o0] = xv.x; sX[ws][o0 + 1] = xv.y;
    __syncwarp();
    float v0 = 0.f, v1 = 0.f;
#pragma unroll 8
    for (int i = 0; i < 64; i++) {
        float xi = sX[ws][i];
        float2 a = *(const float2*)&sC[i * 66 + o0];
        v0 += a.x * xi;
        v1 += a.y * xi;
    }
    float m = fmaxf(v0, v1);
#pragma unroll
    for (int off = 16; off; off >>= 1)
        m = fmaxf(m, __shfl_xor_sync(0xffffffffu, m, off));
    float s = expf(v0 - m) + expf(v1 - m);
#pragma unroll
    for (int off = 16; off; off >>= 1)
        s += __shfl_xor_sync(0xffffffffu, s, off);
    float lse = m + logf(s);
    float2 r;
    r.x = v0 - lse;
    r.y = v1 - lse;
    *(float2*)&out[(size_t)n * NOPEN + o0] = r;
}

// ---------------- launch ----------------
extern "C" void kernel_launch(void* const* d_in, const int* in_sizes, int n_in,
                              void* d_out, int out_size) {
    const float* xn   = (const float*)d_in[0];
    const int*   iInd = (const int*)d_in[1];
    const int*   jInd = (const int*)d_in[2];
    int base = 3;
    if (n_in >= 7 && in_sizes[3] == 1) base = 4;
    const float* K1  = (const float*)d_in[base];
    const float* KN1 = (const float*)d_in[base + 1];
    const float* KC  = (const float*)d_in[base + 2];

    int nN = in_sizes[0] / NNIN;
    int nE = in_sizes[1];

    int nodeBlocks = (nN + 7) / 8;
    long long tiles = ((long long)nE + 31) / 32;
    int edgeBlocks = (int)((tiles + 7) / 8);

    deg_init_kernel<<<(nN + 255) / 256, 256>>>(nN);
    deg_count_kernel<<<(nE + 255) / 256, 256>>>(jInd, nE);
    dinv_kernel<<<(nN + 255) / 256, 256>>>(nN);
    x0_kernel<<<(nN + 255) / 256, 256>>>(xn, K1, nN);
    pre_kernel<<<nodeBlocks, 256>>>(KN1, nN);

    for (int l = 0; l < 4; l++) {
        edge_kernel<<<edgeBlocks, 256>>>(iInd, jInd, nE);
        update_kernel<<<nodeBlocks, 256>>>(KN1, nN, l < 3 ? 1 : 0);
    }
    final_kernel<<<nodeBlocks, 256>>>(KC, (float*)d_out, nN);
}